// round 7
// baseline (speedup 1.0000x reference)
#include <cuda_runtime.h>
#include <math.h>
#include <stdint.h>

// Problem capacities (fixed shapes per reference)
#define NMAXN 50000
#define EMAXE 200000
#define ETOTMAX (EMAXE + NMAXN)
#define GMAXG 1000

// ---------------- scratch (static device memory; no allocations allowed) ----
__device__ float g_bufA[(size_t)NMAXN * 1024];
__device__ float g_bufB[(size_t)NMAXN * 1024];
__device__ float g_bufC[(size_t)NMAXN * 1024];
__device__ float g_alS[NMAXN * 4];
__device__ float g_alD[NMAXN * 4];
__device__ float g_u[512 * 4];
__device__ float g_v[512 * 4];
__device__ int   g_degi[NMAXN];
__device__ int   g_rowptr[NMAXN + 1];
__device__ int   g_cursor[NMAXN];
__device__ int   g_csrsrc[ETOTMAX];
__device__ float g_dinv[NMAXN];
__device__ int   g_gstart[GMAXG + 1];
__device__ float g_bnsum[1024];
__device__ float g_bnsq[1024];
__device__ float g_bnscale[1024];
__device__ float g_bnshift[1024];
__device__ float g_z[GMAXG * 640];
__device__ float g_zf[GMAXG * 128];

// ---------------- CSR build -------------------------------------------------
__global__ void deg_build(const int* __restrict__ ei, int E, int Etot,
                          int* __restrict__ degi)
{
    int e = blockIdx.x * blockDim.x + threadIdx.x;
    if (e >= Etot) return;
    int d = (e < E) ? ei[E + e] : (e - E);
    atomicAdd(degi + d, 1);
}

__global__ void scan_kernel(const int* __restrict__ degi, int* __restrict__ rowptr,
                            int* __restrict__ cursor, int n)
{
    __shared__ int sm[32];
    __shared__ int s_carry;
    int tid = threadIdx.x;
    int lane = tid & 31, w = tid >> 5;
    if (tid == 0) s_carry = 0;
    __syncthreads();
    for (int base = 0; base < n; base += 1024) {
        int i = base + tid;
        int v = (i < n) ? degi[i] : 0;
        int x = v;
#pragma unroll
        for (int o = 1; o < 32; o <<= 1) {
            int y = __shfl_up_sync(0xFFFFFFFFu, x, o);
            if (lane >= o) x += y;
        }
        if (lane == 31) sm[w] = x;
        __syncthreads();
        if (w == 0) {
            int y = sm[lane];
#pragma unroll
            for (int o = 1; o < 32; o <<= 1) {
                int z = __shfl_up_sync(0xFFFFFFFFu, y, o);
                if (lane >= o) y += z;
            }
            sm[lane] = y;
        }
        __syncthreads();
        int incl = x + (w ? sm[w - 1] : 0);
        int excl = incl - v;
        int carry = s_carry;
        if (i < n) { rowptr[i] = carry + excl; cursor[i] = carry + excl; }
        __syncthreads();
        if (tid == 1023) s_carry = carry + incl;
        __syncthreads();
    }
    if (tid == 0) rowptr[n] = s_carry;
}

__global__ void csr_scatter(const int* __restrict__ ei, int E, int Etot,
                            int* __restrict__ cursor, int* __restrict__ csrsrc)
{
    int e = blockIdx.x * blockDim.x + threadIdx.x;
    if (e >= Etot) return;
    int s, d;
    if (e < E) { s = ei[e]; d = ei[E + e]; }
    else       { s = e - E; d = e - E; }
    int pos = atomicAdd(cursor + d, 1);
    csrsrc[pos] = s;
}

__global__ void dinv_kernel(const int* __restrict__ rowptr, float* __restrict__ dinv,
                            int n)
{
    int i = blockIdx.x * blockDim.x + threadIdx.x;
    if (i >= n) return;
    float deg = (float)(rowptr[i + 1] - rowptr[i]);
    dinv[i] = rsqrtf(fmaxf(deg, 1.0f));
}

// graph boundaries from sorted batch
__global__ void gstart_build(const int* __restrict__ batch, int n, int G,
                             int* __restrict__ gstart)
{
    int i = blockIdx.x * blockDim.x + threadIdx.x;
    if (i < n) {
        int b = batch[i];
        int bp = (i > 0) ? batch[i - 1] : -1;
        for (int g = bp + 1; g <= b; g++) gstart[g] = i;
    } else if (i == n) {
        int bl = batch[n - 1];
        for (int g = bl + 1; g <= G; g++) gstart[g] = n;
    }
}

// ---------------- u/v vectors: u[k,h] = sum_c W[k,hC+c]*a[h,c] ---------------
__global__ void uv_build(const float* __restrict__ W, const float* __restrict__ aS,
                         const float* __restrict__ aD, int K, int C,
                         float* __restrict__ u, float* __restrict__ v)
{
    int idx = blockIdx.x * blockDim.x + threadIdx.x;
    int warp = idx >> 5, lane = idx & 31;
    if (warp >= K * 4) return;
    int k = warp >> 2, h = warp & 3;
    const float* wrow = W + (size_t)k * (4 * C) + h * C;
    const float* as = aS + h * C;
    const float* ad = aD + h * C;
    float s = 0.f, d = 0.f;
    for (int c = lane; c < C; c += 32) {
        float wv = wrow[c];
        s += wv * as[c];
        d += wv * ad[c];
    }
#pragma unroll
    for (int o = 16; o; o >>= 1) {
        s += __shfl_xor_sync(0xFFFFFFFFu, s, o);
        d += __shfl_xor_sync(0xFFFFFFFFu, d, o);
    }
    if (lane == 0) { u[k * 4 + h] = s; v[k * 4 + h] = d; }
}

// ---------------- skinny alpha GEMM (layer 1, K=64, fp32 exact) --------------
__global__ __launch_bounds__(256) void alpha_gemm64(
    const float* __restrict__ in, int n,
    const float* __restrict__ u, const float* __restrict__ v,
    float* __restrict__ alS, float* __restrict__ alD)
{
    __shared__ float su[64][4];
    __shared__ float sv[64][4];
    int tid = threadIdx.x;
    if (tid < 64 * 4) { su[tid >> 2][tid & 3] = u[tid]; sv[tid >> 2][tid & 3] = v[tid]; }
    __syncthreads();

    int warp = tid >> 5, lane = tid & 31;
    for (int node = blockIdx.x * 8 + warp; node < n; node += gridDim.x * 8) {
        const float* row = in + (size_t)node * 64;
        float x0 = row[lane], x1 = row[lane + 32];
        float as[4], ad[4];
#pragma unroll
        for (int h = 0; h < 4; h++) {
            as[h] = x0 * su[lane][h] + x1 * su[lane + 32][h];
            ad[h] = x0 * sv[lane][h] + x1 * sv[lane + 32][h];
        }
#pragma unroll
        for (int h = 0; h < 4; h++) {
#pragma unroll
            for (int o = 16; o; o >>= 1) {
                as[h] += __shfl_xor_sync(0xFFFFFFFFu, as[h], o);
                ad[h] += __shfl_xor_sync(0xFFFFFFFFu, ad[h], o);
            }
        }
        if (lane == 0) {
            *(float4*)(alS + (size_t)node * 4) = make_float4(as[0], as[1], as[2], as[3]);
            *(float4*)(alD + (size_t)node * 4) = make_float4(ad[0], ad[1], ad[2], ad[3]);
        }
    }
}

// ---------------- TF32 tensor-core GEMM (3-stage cp.async pipeline) ----------
__device__ __forceinline__ void mma_tf32(float c[4], const float a[4], const float b[2]) {
    asm volatile(
        "mma.sync.aligned.m16n8k8.row.col.f32.tf32.tf32.f32 "
        "{%0,%1,%2,%3}, {%4,%5,%6,%7}, {%8,%9}, {%0,%1,%2,%3};"
        : "+f"(c[0]), "+f"(c[1]), "+f"(c[2]), "+f"(c[3])
        : "r"(__float_as_uint(a[0])), "r"(__float_as_uint(a[1])),
          "r"(__float_as_uint(a[2])), "r"(__float_as_uint(a[3])),
          "r"(__float_as_uint(b[0])), "r"(__float_as_uint(b[1])));
}

__device__ __forceinline__ void cp_async16(float* smem_dst, const float* gmem_src,
                                           bool pred) {
    uint32_t saddr = (uint32_t)__cvta_generic_to_shared(smem_dst);
    int sz = pred ? 16 : 0;
    asm volatile("cp.async.cg.shared.global [%0], [%1], 16, %2;\n"
                 :: "r"(saddr), "l"(gmem_src), "r"(sz));
}

#define ABUF 4608                     // 128 x 36 floats
#define BBUF 4352                     // 32 x 136 floats
#define SSTRIDE (ABUF + BBUF)         // one stage
#define NSTAGE 3
#define SMEM_FLOATS (NSTAGE * SSTRIDE)

// C[M,Nc] = op(A)[M,K] @ B[K,Nc]; op = relu(bn) if BNRELU.
// GROUP: A base shifts by (blockN/128)*K columns (head-blocked input).
// ALPHA: accumulates alS/alD[row*4+head] += sum_col C*aS/aD.
template <bool BNRELU, bool ALPHA, bool GROUP>
__global__ __launch_bounds__(256, 2) void tf32gemm(
    const float* __restrict__ A, const float* __restrict__ B,
    float* __restrict__ C, int M, int Nc, int K,
    int lda, int ldb, int ldc,
    const float* __restrict__ scale, const float* __restrict__ shift,
    const float* __restrict__ aS, const float* __restrict__ aD, int Chead,
    float* __restrict__ alS, float* __restrict__ alD)
{
    extern __shared__ float smem[];

    int tid = threadIdx.x;
    int lane = tid & 31;
    int wid = tid >> 5;
    int warpM = (wid >> 2) * 64;
    int warpN = (wid & 3) * 32;
    int r = lane >> 2;
    int cq = lane & 3;

    int blockM = blockIdx.y * 128;
    int blockN = blockIdx.x * 128;

    if (GROUP) A += (size_t)(blockN >> 7) * K;

    int acol = (tid & 7) * 4;
    int arow0 = tid >> 3;
    int bcol = (tid & 31) * 4;
    int brow0 = tid >> 5;

    float acc[4][4][4];
#pragma unroll
    for (int mt = 0; mt < 4; mt++)
#pragma unroll
        for (int nt = 0; nt < 4; nt++)
#pragma unroll
            for (int i = 0; i < 4; i++) acc[mt][nt][i] = 0.0f;

    int nk = K >> 5;

    auto load_tile = [&](int k0, int buf) {
        float* As = smem + buf * SSTRIDE;
        float* Bs = As + ABUF;
#pragma unroll
        for (int i = 0; i < 4; i++) {
            int row = blockM + arow0 + i * 32;
            cp_async16(&As[(arow0 + i * 32) * 36 + acol],
                       A + (size_t)row * lda + k0 + acol, row < M);
        }
#pragma unroll
        for (int i = 0; i < 4; i++) {
            int kr = brow0 + i * 8;
            cp_async16(&Bs[kr * 136 + bcol],
                       B + (size_t)(k0 + kr) * ldb + blockN + bcol, true);
        }
        asm volatile("cp.async.commit_group;\n");
    };

    load_tile(0, 0);
    if (nk > 1) load_tile(32, 1);

    for (int kt = 0; kt < nk; kt++) {
        if (kt + 1 < nk) asm volatile("cp.async.wait_group 1;\n");
        else             asm volatile("cp.async.wait_group 0;\n");
        __syncthreads();
        if (kt + 2 < nk) load_tile((kt + 2) << 5, (kt + 2) % NSTAGE);

        const float* As = smem + (kt % NSTAGE) * SSTRIDE;
        const float* Bs = As + ABUF;
        int k0 = kt << 5;

        float scv[8], shv[8];
        if (BNRELU) {
#pragma unroll
            for (int kk = 0; kk < 4; kk++) {
                scv[kk]     = scale[k0 + kk * 8 + cq];
                scv[kk + 4] = scale[k0 + kk * 8 + cq + 4];
                shv[kk]     = shift[k0 + kk * 8 + cq];
                shv[kk + 4] = shift[k0 + kk * 8 + cq + 4];
            }
        }

#pragma unroll
        for (int kk = 0; kk < 4; kk++) {
            int kb = kk * 8;
            float a[4][4], b[4][2];
#pragma unroll
            for (int mt = 0; mt < 4; mt++) {
                int m = warpM + mt * 16 + r;
                float a0 = As[m * 36 + kb + cq];
                float a1 = As[(m + 8) * 36 + kb + cq];
                float a2 = As[m * 36 + kb + cq + 4];
                float a3 = As[(m + 8) * 36 + kb + cq + 4];
                if (BNRELU) {
                    a0 = fmaxf(fmaf(a0, scv[kk], shv[kk]), 0.f);
                    a1 = fmaxf(fmaf(a1, scv[kk], shv[kk]), 0.f);
                    a2 = fmaxf(fmaf(a2, scv[kk + 4], shv[kk + 4]), 0.f);
                    a3 = fmaxf(fmaf(a3, scv[kk + 4], shv[kk + 4]), 0.f);
                }
                a[mt][0] = a0; a[mt][1] = a1; a[mt][2] = a2; a[mt][3] = a3;
            }
#pragma unroll
            for (int nt = 0; nt < 4; nt++) {
                int nn = warpN + nt * 8 + r;
                b[nt][0] = Bs[(kb + cq) * 136 + nn];
                b[nt][1] = Bs[(kb + cq + 4) * 136 + nn];
            }
#pragma unroll
            for (int mt = 0; mt < 4; mt++)
#pragma unroll
                for (int nt = 0; nt < 4; nt++)
                    mma_tf32(acc[mt][nt], a[mt], b[nt]);
        }
    }

#pragma unroll
    for (int mt = 0; mt < 4; mt++) {
        int row0 = blockM + warpM + mt * 16 + r;
#pragma unroll
        for (int nt = 0; nt < 4; nt++) {
            int col = blockN + warpN + nt * 8 + cq * 2;
            if (row0 < M)
                *(float2*)(C + (size_t)row0 * ldc + col) =
                    make_float2(acc[mt][nt][0], acc[mt][nt][1]);
            if (row0 + 8 < M)
                *(float2*)(C + (size_t)(row0 + 8) * ldc + col) =
                    make_float2(acc[mt][nt][2], acc[mt][nt][3]);
        }
    }

    if (ALPHA) {
        int head = blockN / Chead;
        float ws[4][2], wd[4][2];
#pragma unroll
        for (int nt = 0; nt < 4; nt++) {
            int col = blockN + warpN + nt * 8 + cq * 2;
            int c = col - head * Chead;
            ws[nt][0] = aS[head * Chead + c];
            ws[nt][1] = aS[head * Chead + c + 1];
            wd[nt][0] = aD[head * Chead + c];
            wd[nt][1] = aD[head * Chead + c + 1];
        }
#pragma unroll
        for (int mt = 0; mt < 4; mt++) {
            float ps0 = 0.f, pd0 = 0.f, ps1 = 0.f, pd1 = 0.f;
#pragma unroll
            for (int nt = 0; nt < 4; nt++) {
                ps0 += acc[mt][nt][0] * ws[nt][0] + acc[mt][nt][1] * ws[nt][1];
                pd0 += acc[mt][nt][0] * wd[nt][0] + acc[mt][nt][1] * wd[nt][1];
                ps1 += acc[mt][nt][2] * ws[nt][0] + acc[mt][nt][3] * ws[nt][1];
                pd1 += acc[mt][nt][2] * wd[nt][0] + acc[mt][nt][3] * wd[nt][1];
            }
#pragma unroll
            for (int o = 1; o < 4; o <<= 1) {
                ps0 += __shfl_xor_sync(0xFFFFFFFFu, ps0, o);
                pd0 += __shfl_xor_sync(0xFFFFFFFFu, pd0, o);
                ps1 += __shfl_xor_sync(0xFFFFFFFFu, ps1, o);
                pd1 += __shfl_xor_sync(0xFFFFFFFFu, pd1, o);
            }
            if (cq == 0) {
                int row0 = blockM + warpM + mt * 16 + r;
                if (row0 < M) {
                    atomicAdd(alS + (size_t)row0 * 4 + head, ps0);
                    atomicAdd(alD + (size_t)row0 * 4 + head, pd0);
                }
                if (row0 + 8 < M) {
                    atomicAdd(alS + (size_t)(row0 + 8) * 4 + head, ps1);
                    atomicAdd(alD + (size_t)(row0 + 8) * 4 + head, pd1);
                }
            }
        }
    }
}

// ---------------- fp32 SGEMM (small head GEMMs) ------------------------------
template <bool RELU>
__global__ __launch_bounds__(256) void sgemm(
    const float* __restrict__ A, const float* __restrict__ B,
    const float* __restrict__ bias, float* __restrict__ C,
    int M, int Nc, int K, int lda, int ldc)
{
    __shared__ float As[8][128];
    __shared__ float Bs[8][128];

    int tid = threadIdx.x;
    int bx = blockIdx.x;
    int by = blockIdx.y;

    int tx = tid % 16;
    int ty = tid / 16;

    int rowA = by * 128 + tid / 2;
    int colA = (tid % 2) * 4;
    int rowB = tid / 32;
    int colB = (tid % 32) * 4;

    float acc[8][8];
#pragma unroll
    for (int i = 0; i < 8; i++)
#pragma unroll
        for (int j = 0; j < 8; j++) acc[i][j] = 0.0f;

    for (int k0 = 0; k0 < K; k0 += 8) {
        float4 av = make_float4(0.f, 0.f, 0.f, 0.f);
        if (rowA < M)
            av = *(const float4*)(A + (size_t)rowA * lda + k0 + colA);
        As[colA + 0][tid / 2] = av.x;
        As[colA + 1][tid / 2] = av.y;
        As[colA + 2][tid / 2] = av.z;
        As[colA + 3][tid / 2] = av.w;

        float4 bv = *(const float4*)(B + (size_t)(k0 + rowB) * Nc + bx * 128 + colB);
        *(float4*)(&Bs[rowB][colB]) = bv;

        __syncthreads();

#pragma unroll
        for (int kk = 0; kk < 8; kk++) {
            float ra[8], rb[8];
#pragma unroll
            for (int i = 0; i < 8; i++) ra[i] = As[kk][ty * 8 + i];
#pragma unroll
            for (int j = 0; j < 8; j++) rb[j] = Bs[kk][tx * 8 + j];
#pragma unroll
            for (int i = 0; i < 8; i++)
#pragma unroll
                for (int j = 0; j < 8; j++) acc[i][j] = fmaf(ra[i], rb[j], acc[i][j]);
        }
        __syncthreads();
    }

#pragma unroll
    for (int i = 0; i < 8; i++) {
        int row = by * 128 + ty * 8 + i;
        if (row >= M) continue;
#pragma unroll
        for (int j = 0; j < 8; j++) {
            int col = bx * 128 + tx * 8 + j;
            float v = acc[i][j];
            if (bias) v += bias[col];
            if (RELU) v = v > 0.f ? v : 0.f;
            C[(size_t)row * ldc + col] = v;
        }
    }
}

// ---- GAT layer 1 input-space gather: agg[d, h*64+c] = sum alpha*x[src,c] ----
__global__ __launch_bounds__(64) void gat_agg_in64(
    const int* __restrict__ rowptr, const int* __restrict__ csrsrc,
    const float* __restrict__ alS, const float* __restrict__ alD,
    const float* __restrict__ in, float* __restrict__ agg)
{
    constexpr int NT = 64;
    __shared__ float s_red[8];
    __shared__ float s_bm[4];
    __shared__ float s_binv[4];
    __shared__ float s_al[16][4];
    __shared__ int   s_src[16];

    int d = blockIdx.x;
    int tid = threadIdx.x;
    int lane = tid & 31, w = tid >> 5;
    int beg = rowptr[d], end = rowptr[d + 1];

    float4 ad4 = *(const float4*)(alD + (size_t)d * 4);
    float adv[4] = {ad4.x, ad4.y, ad4.z, ad4.w};

    float mx[4] = {-INFINITY, -INFINITY, -INFINITY, -INFINITY};
    for (int i = beg + tid; i < end; i += NT) {
        int s = csrsrc[i];
        float4 as4 = *(const float4*)(alS + (size_t)s * 4);
        float l[4] = {as4.x + adv[0], as4.y + adv[1], as4.z + adv[2], as4.w + adv[3]};
#pragma unroll
        for (int hh = 0; hh < 4; hh++) {
            float t = l[hh];
            t = t > 0.f ? t : 0.2f * t;
            mx[hh] = fmaxf(mx[hh], t);
        }
    }
#pragma unroll
    for (int hh = 0; hh < 4; hh++)
#pragma unroll
        for (int o = 16; o; o >>= 1)
            mx[hh] = fmaxf(mx[hh], __shfl_xor_sync(0xFFFFFFFFu, mx[hh], o));
    if (lane == 0)
#pragma unroll
        for (int hh = 0; hh < 4; hh++) s_red[w * 4 + hh] = mx[hh];
    __syncthreads();
    if (tid < 4) s_bm[tid] = fmaxf(s_red[tid], s_red[4 + tid]);
    __syncthreads();
    float bm[4] = {s_bm[0], s_bm[1], s_bm[2], s_bm[3]};

    float sme[4] = {0.f, 0.f, 0.f, 0.f};
    for (int i = beg + tid; i < end; i += NT) {
        int s = csrsrc[i];
        float4 as4 = *(const float4*)(alS + (size_t)s * 4);
        float l[4] = {as4.x + adv[0], as4.y + adv[1], as4.z + adv[2], as4.w + adv[3]};
#pragma unroll
        for (int hh = 0; hh < 4; hh++) {
            float t = l[hh];
            t = t > 0.f ? t : 0.2f * t;
            sme[hh] += expf(t - bm[hh]);
        }
    }
#pragma unroll
    for (int hh = 0; hh < 4; hh++)
#pragma unroll
        for (int o = 16; o; o >>= 1)
            sme[hh] += __shfl_xor_sync(0xFFFFFFFFu, sme[hh], o);
    if (lane == 0)
#pragma unroll
        for (int hh = 0; hh < 4; hh++) s_red[w * 4 + hh] = sme[hh];
    __syncthreads();
    if (tid < 4) s_binv[tid] = 1.0f / fmaxf(s_red[tid] + s_red[4 + tid], 1e-16f);
    __syncthreads();

    float acc[4] = {0.f, 0.f, 0.f, 0.f};
    for (int c0 = beg; c0 < end; c0 += 16) {
        int cnt = min(16, end - c0);
        if (tid < cnt * 4) {
            int j = tid >> 2, hh = tid & 3;
            int s = csrsrc[c0 + j];
            if (hh == 0) s_src[j] = s;
            float t = alS[(size_t)s * 4 + hh] + adv[hh];
            t = t > 0.f ? t : 0.2f * t;
            s_al[j][hh] = expf(t - s_bm[hh]) * s_binv[hh];
        }
        __syncthreads();
        for (int j = 0; j < cnt; j++) {
            float v = in[(size_t)s_src[j] * 64 + tid];
#pragma unroll
            for (int hh = 0; hh < 4; hh++)
                acc[hh] = fmaf(s_al[j][hh], v, acc[hh]);
        }
        __syncthreads();
    }

#pragma unroll
    for (int hh = 0; hh < 4; hh++)
        agg[(size_t)d * 256 + hh * 64 + tid] = acc[hh];
}

// ---- fused per-destination GAT softmax + gather (output space, NT threads) --
template <int HC, int NT>
__global__ __launch_bounds__(NT) void gat_gather(
    const int* __restrict__ rowptr, const int* __restrict__ csrsrc,
    const float* __restrict__ alS, const float* __restrict__ alD,
    const float* __restrict__ h, float* __restrict__ out)
{
    constexpr int VEC = HC / (4 * NT);
    constexpr int CPH = HC / 4;
    constexpr int NW = NT / 32;
    constexpr int CHUNK = NT / 4;

    __shared__ float s_red[NW * 4];
    __shared__ float s_bm[4];
    __shared__ float s_binv[4];
    __shared__ float s_al[CHUNK][4];
    __shared__ int   s_src[CHUNK];

    int d = blockIdx.x;
    int tid = threadIdx.x;
    int lane = tid & 31, w = tid >> 5;
    int beg = rowptr[d], end = rowptr[d + 1];

    float4 ad4 = *(const float4*)(alD + (size_t)d * 4);
    float adv[4] = {ad4.x, ad4.y, ad4.z, ad4.w};

    float mx[4] = {-INFINITY, -INFINITY, -INFINITY, -INFINITY};
    for (int i = beg + tid; i < end; i += NT) {
        int s = csrsrc[i];
        float4 as4 = *(const float4*)(alS + (size_t)s * 4);
        float l[4] = {as4.x + adv[0], as4.y + adv[1], as4.z + adv[2], as4.w + adv[3]};
#pragma unroll
        for (int hh = 0; hh < 4; hh++) {
            float t = l[hh];
            t = t > 0.f ? t : 0.2f * t;
            mx[hh] = fmaxf(mx[hh], t);
        }
    }
#pragma unroll
    for (int hh = 0; hh < 4; hh++)
#pragma unroll
        for (int o = 16; o; o >>= 1)
            mx[hh] = fmaxf(mx[hh], __shfl_xor_sync(0xFFFFFFFFu, mx[hh], o));
    if (lane == 0)
#pragma unroll
        for (int hh = 0; hh < 4; hh++) s_red[w * 4 + hh] = mx[hh];
    __syncthreads();
    if (tid < 4) {
        float r = -INFINITY;
#pragma unroll
        for (int ww = 0; ww < NW; ww++) r = fmaxf(r, s_red[ww * 4 + tid]);
        s_bm[tid] = r;
    }
    __syncthreads();
    float bm[4] = {s_bm[0], s_bm[1], s_bm[2], s_bm[3]};

    float sme[4] = {0.f, 0.f, 0.f, 0.f};
    for (int i = beg + tid; i < end; i += NT) {
        int s = csrsrc[i];
        float4 as4 = *(const float4*)(alS + (size_t)s * 4);
        float l[4] = {as4.x + adv[0], as4.y + adv[1], as4.z + adv[2], as4.w + adv[3]};
#pragma unroll
        for (int hh = 0; hh < 4; hh++) {
            float t = l[hh];
            t = t > 0.f ? t : 0.2f * t;
            sme[hh] += expf(t - bm[hh]);
        }
    }
#pragma unroll
    for (int hh = 0; hh < 4; hh++)
#pragma unroll
        for (int o = 16; o; o >>= 1)
            sme[hh] += __shfl_xor_sync(0xFFFFFFFFu, sme[hh], o);
    if (lane == 0)
#pragma unroll
        for (int hh = 0; hh < 4; hh++) s_red[w * 4 + hh] = sme[hh];
    __syncthreads();
    if (tid < 4) {
        float r = 0.f;
#pragma unroll
        for (int ww = 0; ww < NW; ww++) r += s_red[ww * 4 + tid];
        s_binv[tid] = 1.0f / fmaxf(r, 1e-16f);
    }
    __syncthreads();

    float4 acc[VEC];
#pragma unroll
    for (int v = 0; v < VEC; v++) acc[v] = make_float4(0.f, 0.f, 0.f, 0.f);

    int headOf[VEC];
#pragma unroll
    for (int v = 0; v < VEC; v++) headOf[v] = (tid * 4 + v * NT * 4) / CPH;

    for (int c0 = beg; c0 < end; c0 += CHUNK) {
        int cnt = min(CHUNK, end - c0);
        if (tid < cnt * 4) {
            int j = tid >> 2, hh = tid & 3;
            int s = csrsrc[c0 + j];
            if (hh == 0) s_src[j] = s;
            float t = alS[(size_t)s * 4 + hh] + adv[hh];
            t = t > 0.f ? t : 0.2f * t;
            s_al[j][hh] = expf(t - s_bm[hh]) * s_binv[hh];
        }
        __syncthreads();
        for (int j = 0; j < cnt; j++) {
            int s = s_src[j];
            const float4* hp = (const float4*)(h + (size_t)s * HC);
#pragma unroll
            for (int v = 0; v < VEC; v++) {
                float a = s_al[j][headOf[v]];
                float4 hv = hp[tid + v * NT];
                acc[v].x = fmaf(a, hv.x, acc[v].x);
                acc[v].y = fmaf(a, hv.y, acc[v].y);
                acc[v].z = fmaf(a, hv.z, acc[v].z);
                acc[v].w = fmaf(a, hv.w, acc[v].w);
            }
        }
        __syncthreads();
    }

    float4* op = (float4*)(out + (size_t)d * HC);
#pragma unroll
    for (int v = 0; v < VEC; v++) op[tid + v * NT] = acc[v];
}

// ---------------- GCN gather -------------------------------------------------
__global__ __launch_bounds__(64) void gcn_gather(
    const int* __restrict__ rowptr, const int* __restrict__ csrsrc,
    const float* __restrict__ dinv, const float* __restrict__ h,
    float* __restrict__ out)
{
    int d = blockIdx.x;
    int tid = threadIdx.x;
    int beg = rowptr[d], end = rowptr[d + 1];
    float dd = dinv[d];

    float4 acc = make_float4(0.f, 0.f, 0.f, 0.f);
    for (int i = beg; i < end; i++) {
        int s = csrsrc[i];
        float nrm = dinv[s] * dd;
        float4 v = *(const float4*)(h + (size_t)s * 256 + tid * 4);
        acc.x = fmaf(nrm, v.x, acc.x);
        acc.y = fmaf(nrm, v.y, acc.y);
        acc.z = fmaf(nrm, v.z, acc.z);
        acc.w = fmaf(nrm, v.w, acc.w);
    }
    *(float4*)(out + (size_t)d * 256 + tid * 4) = acc;
}

// ---------------- BatchNorm -------------------------------------------------
__global__ void bn_stats(const float* __restrict__ x, int rows, int K,
                         float* __restrict__ sum, float* __restrict__ sq)
{
    int col = blockIdx.x * blockDim.x + threadIdx.x;
    float s = 0.f, q = 0.f;
    for (int r = blockIdx.y; r < rows; r += gridDim.y) {
        float v = x[(size_t)r * K + col];
        s += v;
        q += v * v;
    }
    atomicAdd(sum + col, s);
    atomicAdd(sq + col, q);
}

__global__ void bn_finalize(const float* __restrict__ sum, const float* __restrict__ sq,
                            const float* __restrict__ g, const float* __restrict__ b,
                            int rows, int K, float* __restrict__ scale,
                            float* __restrict__ shift)
{
    int c = blockIdx.x * blockDim.x + threadIdx.x;
    if (c >= K) return;
    float inv_n = 1.0f / (float)rows;
    float mu = sum[c] * inv_n;
    float var = sq[c] * inv_n - mu * mu;
    float sc = g[c] * rsqrtf(var + 1e-5f);
    scale[c] = sc;
    shift[c] = b[c] - mu * sc;
}

__global__ void bn_apply_relu(float* __restrict__ x, const float* __restrict__ scale,
                              const float* __restrict__ shift, size_t total, int K)
{
    for (size_t i = (size_t)blockIdx.x * blockDim.x + threadIdx.x; i < total;
         i += (size_t)gridDim.x * blockDim.x) {
        int c = (int)(i % K);
        float v = x[i] * scale[c] + shift[c];
        x[i] = v > 0.f ? v : 0.f;
    }
}

// ---------------- Pooling: one block per graph (batch sorted, no atomics) ----
__global__ __launch_bounds__(256) void pool_graph(
    const float* __restrict__ h, const int* __restrict__ gstart,
    const float* __restrict__ scale, const float* __restrict__ shift,
    float* __restrict__ z)
{
    int g = blockIdx.x;
    int c = threadIdx.x;
    int beg = gstart[g], end = gstart[g + 1];
    float sc = scale[c], sh = shift[c];
    float sum = 0.f, mx = 0.f;
    for (int r = beg; r < end; r++) {
        float v = fmaxf(fmaf(h[(size_t)r * 256 + c], sc, sh), 0.f);
        sum += v;
        mx = fmaxf(mx, v);
    }
    float cnt = (float)(end - beg);
    z[(size_t)g * 640 + c] = sum / fmaxf(cnt, 1.0f);
    z[(size_t)g * 640 + 256 + c] = mx;
}

// ---------------- Head -------------------------------------------------------
__global__ void head_final(const float* __restrict__ zf, const float* __restrict__ Wf2,
                           const float* __restrict__ bf2, float* __restrict__ out)
{
    int g = blockIdx.x;
    int t = threadIdx.x;
    float v = zf[(size_t)g * 128 + t] * Wf2[t];
#pragma unroll
    for (int o = 16; o; o >>= 1) v += __shfl_down_sync(0xFFFFFFFFu, v, o);
    __shared__ float sm[4];
    if ((t & 31) == 0) sm[t >> 5] = v;
    __syncthreads();
    if (t == 0) {
        float s = sm[0] + sm[1] + sm[2] + sm[3] + bf2[0];
        out[g] = 1.0f / (1.0f + expf(-s));
    }
}

// ---------------- launch ------------------------------------------------------
extern "C" void kernel_launch(void* const* d_in, const int* in_sizes, int n_in,
                              void* d_out, int out_size)
{
    const float* x    = (const float*)d_in[0];
    const int*   ei   = (const int*)d_in[1];
    const int*   batch= (const int*)d_in[2];
    const float* fp   = (const float*)d_in[3];
    const float* W1   = (const float*)d_in[4];
    const float* a1s  = (const float*)d_in[5];
    const float* a1d  = (const float*)d_in[6];
    const float* bn1g = (const float*)d_in[8];
    const float* bn1b = (const float*)d_in[9];
    const float* W2   = (const float*)d_in[10];
    const float* a2s  = (const float*)d_in[11];
    const float* a2d  = (const float*)d_in[12];
    const float* bn2g = (const float*)d_in[14];
    const float* bn2b = (const float*)d_in[15];
    const float* Wg   = (const float*)d_in[16];
    const float* bn3g = (const float*)d_in[18];
    const float* bn3b = (const float*)d_in[19];
    const float* Ws   = (const float*)d_in[20];
    const float* bs   = (const float*)d_in[21];
    const float* Wf1  = (const float*)d_in[22];
    const float* bnfg = (const float*)d_in[24];
    const float* bnfb = (const float*)d_in[25];
    const float* Wf2  = (const float*)d_in[26];
    const float* bf2  = (const float*)d_in[27];
    float* out = (float*)d_out;

    int n    = in_sizes[0] / 64;
    int E    = in_sizes[1] / 2;
    int Etot = E + n;
    int G    = in_sizes[3] / 128;

    float *bufA, *bufB, *bufC, *alS, *alD, *dinv, *uu, *vv;
    float *bnsum, *bnsq, *bnscale, *bnshift, *z, *zf;
    int *degi, *rowptr, *cursor, *csrsrc, *gstart;
    cudaGetSymbolAddress((void**)&bufA, g_bufA);
    cudaGetSymbolAddress((void**)&bufB, g_bufB);
    cudaGetSymbolAddress((void**)&bufC, g_bufC);
    cudaGetSymbolAddress((void**)&alS, g_alS);
    cudaGetSymbolAddress((void**)&alD, g_alD);
    cudaGetSymbolAddress((void**)&uu, g_u);
    cudaGetSymbolAddress((void**)&vv, g_v);
    cudaGetSymbolAddress((void**)&degi, g_degi);
    cudaGetSymbolAddress((void**)&rowptr, g_rowptr);
    cudaGetSymbolAddress((void**)&cursor, g_cursor);
    cudaGetSymbolAddress((void**)&csrsrc, g_csrsrc);
    cudaGetSymbolAddress((void**)&dinv, g_dinv);
    cudaGetSymbolAddress((void**)&gstart, g_gstart);
    cudaGetSymbolAddress((void**)&bnsum, g_bnsum);
    cudaGetSymbolAddress((void**)&bnsq, g_bnsq);
    cudaGetSymbolAddress((void**)&bnscale, g_bnscale);
    cudaGetSymbolAddress((void**)&bnshift, g_bnshift);
    cudaGetSymbolAddress((void**)&z, g_z);
    cudaGetSymbolAddress((void**)&zf, g_zf);

    size_t smem_bytes = SMEM_FLOATS * sizeof(float);
    static bool attr_done = false;
    if (!attr_done) {
        cudaFuncSetAttribute(tf32gemm<false, false, true>,
                             cudaFuncAttributeMaxDynamicSharedMemorySize, (int)smem_bytes);
        cudaFuncSetAttribute(tf32gemm<true, true, false>,
                             cudaFuncAttributeMaxDynamicSharedMemorySize, (int)smem_bytes);
        cudaFuncSetAttribute(tf32gemm<true, false, false>,
                             cudaFuncAttributeMaxDynamicSharedMemorySize, (int)smem_bytes);
        attr_done = true;
    }

    auto gemm = [&](const float* A, const float* B, const float* bias, float* C,
                    int M, int Nc, int K, int lda, int ldc, bool relu) {
        dim3 grid(Nc / 128, (M + 127) / 128);
        if (relu) sgemm<true><<<grid, 256>>>(A, B, bias, C, M, Nc, K, lda, ldc);
        else      sgemm<false><<<grid, 256>>>(A, B, bias, C, M, Nc, K, lda, ldc);
    };

    auto bnstats = [&](const float* Xp, int rows, int K, const float* gg,
                       const float* bb) {
        cudaMemsetAsync(bnsum, 0, K * sizeof(float));
        cudaMemsetAsync(bnsq, 0, K * sizeof(float));
        dim3 g1(K / 128, 128);
        bn_stats<<<g1, 128>>>(Xp, rows, K, bnsum, bnsq);
        bn_finalize<<<(K + 127) / 128, 128>>>(bnsum, bnsq, gg, bb, rows, K,
                                              bnscale, bnshift);
    };

    // ---- CSR build (dst-sorted), reused by GAT1/GAT2/GCN; graph boundaries
    cudaMemsetAsync(degi, 0, n * sizeof(int));
    deg_build<<<(Etot + 255) / 256, 256>>>(ei, E, Etot, degi);
    scan_kernel<<<1, 1024>>>(degi, rowptr, cursor, n);
    csr_scatter<<<(Etot + 255) / 256, 256>>>(ei, E, Etot, cursor, csrsrc);
    dinv_kernel<<<(n + 255) / 256, 256>>>(rowptr, dinv, n);
    gstart_build<<<(n + 256) / 256, 256>>>(batch, n, G, gstart);

    // ---- GAT layer 1 (input-space): alphas exact via u=W1·a; gather x; GEMM
    uv_build<<<(64 * 4 * 32 + 255) / 256, 256>>>(W1, a1s, a1d, 64, 128, uu, vv);
    alpha_gemm64<<<(n + 7) / 8, 256>>>(x, n, uu, vv, alS, alD);
    gat_agg_in64<<<n, 64>>>(rowptr, csrsrc, alS, alD, x, bufA);
    {
        dim3 grid(4, (n + 127) / 128);
        tf32gemm<false, false, true><<<grid, 256, smem_bytes>>>(
            bufA, W1, bufB, n, 512, 64, 256, 512, 512,
            nullptr, nullptr, nullptr, nullptr, 128, nullptr, nullptr);
    }
    bnstats(bufB, n, 512, bn1g, bn1b);

    // ---- GAT layer 2: bufC = relu(bn(bufB))@W2 (+ fused alphas); gather -> bufA
    cudaMemsetAsync(alS, 0, (size_t)n * 4 * sizeof(float));
    cudaMemsetAsync(alD, 0, (size_t)n * 4 * sizeof(float));
    {
        dim3 grid(8, (n + 127) / 128);
        tf32gemm<true, true, false><<<grid, 256, smem_bytes>>>(
            bufB, W2, bufC, n, 1024, 512, 512, 1024, 1024,
            bnscale, bnshift, a2s, a2d, 256, alS, alD);
    }
    gat_gather<1024, 256><<<n, 256>>>(rowptr, csrsrc, alS, alD, bufC, bufA);
    bnstats(bufA, n, 1024, bn2g, bn2b);

    // ---- GCN: bufB[N,256] = relu(bn(bufA))@Wg; gather -> bufC; BN stats
    {
        dim3 grid(2, (n + 127) / 128);
        tf32gemm<true, false, false><<<grid, 256, smem_bytes>>>(
            bufA, Wg, bufB, n, 256, 1024, 1024, 256, 256,
            bnscale, bnshift, nullptr, nullptr, 256, nullptr, nullptr);
    }
    gcn_gather<<<n, 64>>>(rowptr, csrsrc, dinv, bufB, bufC);
    bnstats(bufC, n, 256, bn3g, bn3b);

    // ---- Pooling into z[G,640] (block per graph; BN+relu on the fly)
    pool_graph<<<G, 256>>>(bufC, gstart, bnscale, bnshift, z);

    // ---- solvent MLP: relu(fp @ Ws + bs) -> z[:,512:640]
    gemm(fp, Ws, bs, z + 512, G, 128, 128, 128, 640, true);

    // ---- head: zf = z @ Wf1 (bf1 cancels under BN); BN; relu; sigmoid
    gemm(z, Wf1, nullptr, zf, G, 128, 640, 640, 128, false);
    {
        cudaMemsetAsync(bnsum, 0, 128 * sizeof(float));
        cudaMemsetAsync(bnsq, 0, 128 * sizeof(float));
        dim3 g1(1, 128);
        bn_stats<<<g1, 128>>>(zf, G, 128, bnsum, bnsq);
        bn_finalize<<<1, 128>>>(bnsum, bnsq, bnfg, bnfb, G, 128, bnscale, bnshift);
        bn_apply_relu<<<((size_t)G * 128 + 255) / 256, 256>>>(zf, bnscale, bnshift,
                                                              (size_t)G * 128, 128);
    }
    head_final<<<G, 128>>>(zf, Wf2, bf2, out);
}

// round 8
// speedup vs baseline: 1.0477x; 1.0477x over previous
#include <cuda_runtime.h>
#include <math.h>
#include <stdint.h>

// Problem capacities (fixed shapes per reference)
#define NMAXN 50000
#define EMAXE 200000
#define ETOTMAX (EMAXE + NMAXN)
#define GMAXG 1000

// ---------------- scratch (static device memory; no allocations allowed) ----
__device__ float g_bufA[(size_t)NMAXN * 1024];
__device__ float g_bufB[(size_t)NMAXN * 1024];
__device__ float g_bufC[(size_t)NMAXN * 1024];
__device__ float g_alS[NMAXN * 4];
__device__ float g_alD[NMAXN * 4];
__device__ float g_u[512 * 4];
__device__ float g_v[512 * 4];
__device__ int   g_degi[NMAXN];
__device__ int   g_rowptr[NMAXN + 1];
__device__ int   g_cursor[NMAXN];
__device__ int   g_csrsrc[ETOTMAX];
__device__ float g_dinv[NMAXN];
__device__ int   g_gstart[GMAXG + 1];
__device__ float g_bnsum[1024];
__device__ float g_bnsq[1024];
__device__ float g_bnscale[1024];
__device__ float g_bnshift[1024];
__device__ float g_z[GMAXG * 640];
__device__ float g_zf[GMAXG * 128];

// ---------------- CSR build -------------------------------------------------
__global__ void deg_build(const int* __restrict__ ei, int E, int Etot,
                          int* __restrict__ degi)
{
    int e = blockIdx.x * blockDim.x + threadIdx.x;
    if (e >= Etot) return;
    int d = (e < E) ? ei[E + e] : (e - E);
    atomicAdd(degi + d, 1);
}

__global__ void scan_kernel(const int* __restrict__ degi, int* __restrict__ rowptr,
                            int* __restrict__ cursor, int n)
{
    __shared__ int sm[32];
    __shared__ int s_carry;
    int tid = threadIdx.x;
    int lane = tid & 31, w = tid >> 5;
    if (tid == 0) s_carry = 0;
    __syncthreads();
    for (int base = 0; base < n; base += 1024) {
        int i = base + tid;
        int v = (i < n) ? degi[i] : 0;
        int x = v;
#pragma unroll
        for (int o = 1; o < 32; o <<= 1) {
            int y = __shfl_up_sync(0xFFFFFFFFu, x, o);
            if (lane >= o) x += y;
        }
        if (lane == 31) sm[w] = x;
        __syncthreads();
        if (w == 0) {
            int y = sm[lane];
#pragma unroll
            for (int o = 1; o < 32; o <<= 1) {
                int z = __shfl_up_sync(0xFFFFFFFFu, y, o);
                if (lane >= o) y += z;
            }
            sm[lane] = y;
        }
        __syncthreads();
        int incl = x + (w ? sm[w - 1] : 0);
        int excl = incl - v;
        int carry = s_carry;
        if (i < n) { rowptr[i] = carry + excl; cursor[i] = carry + excl; }
        __syncthreads();
        if (tid == 1023) s_carry = carry + incl;
        __syncthreads();
    }
    if (tid == 0) rowptr[n] = s_carry;
}

__global__ void csr_scatter(const int* __restrict__ ei, int E, int Etot,
                            int* __restrict__ cursor, int* __restrict__ csrsrc)
{
    int e = blockIdx.x * blockDim.x + threadIdx.x;
    if (e >= Etot) return;
    int s, d;
    if (e < E) { s = ei[e]; d = ei[E + e]; }
    else       { s = e - E; d = e - E; }
    int pos = atomicAdd(cursor + d, 1);
    csrsrc[pos] = s;
}

__global__ void dinv_kernel(const int* __restrict__ rowptr, float* __restrict__ dinv,
                            int n)
{
    int i = blockIdx.x * blockDim.x + threadIdx.x;
    if (i >= n) return;
    float deg = (float)(rowptr[i + 1] - rowptr[i]);
    dinv[i] = rsqrtf(fmaxf(deg, 1.0f));
}

// graph boundaries from sorted batch
__global__ void gstart_build(const int* __restrict__ batch, int n, int G,
                             int* __restrict__ gstart)
{
    int i = blockIdx.x * blockDim.x + threadIdx.x;
    if (i < n) {
        int b = batch[i];
        int bp = (i > 0) ? batch[i - 1] : -1;
        for (int g = bp + 1; g <= b; g++) gstart[g] = i;
    } else if (i == n) {
        int bl = batch[n - 1];
        for (int g = bl + 1; g <= G; g++) gstart[g] = n;
    }
}

// ---------------- u/v vectors: u[k,h] = sum_c W[k,hC+c]*a[h,c] ---------------
__global__ void uv_build(const float* __restrict__ W, const float* __restrict__ aS,
                         const float* __restrict__ aD, int K, int C,
                         float* __restrict__ u, float* __restrict__ v)
{
    int idx = blockIdx.x * blockDim.x + threadIdx.x;
    int warp = idx >> 5, lane = idx & 31;
    if (warp >= K * 4) return;
    int k = warp >> 2, h = warp & 3;
    const float* wrow = W + (size_t)k * (4 * C) + h * C;
    const float* as = aS + h * C;
    const float* ad = aD + h * C;
    float s = 0.f, d = 0.f;
    for (int c = lane; c < C; c += 32) {
        float wv = wrow[c];
        s += wv * as[c];
        d += wv * ad[c];
    }
#pragma unroll
    for (int o = 16; o; o >>= 1) {
        s += __shfl_xor_sync(0xFFFFFFFFu, s, o);
        d += __shfl_xor_sync(0xFFFFFFFFu, d, o);
    }
    if (lane == 0) { u[k * 4 + h] = s; v[k * 4 + h] = d; }
}

// ---------------- skinny alpha GEMM (layer 1, K=64, fp32 exact) --------------
__global__ __launch_bounds__(256) void alpha_gemm64(
    const float* __restrict__ in, int n,
    const float* __restrict__ u, const float* __restrict__ v,
    float* __restrict__ alS, float* __restrict__ alD)
{
    __shared__ float su[64][4];
    __shared__ float sv[64][4];
    int tid = threadIdx.x;
    if (tid < 64 * 4) { su[tid >> 2][tid & 3] = u[tid]; sv[tid >> 2][tid & 3] = v[tid]; }
    __syncthreads();

    int warp = tid >> 5, lane = tid & 31;
    for (int node = blockIdx.x * 8 + warp; node < n; node += gridDim.x * 8) {
        const float* row = in + (size_t)node * 64;
        float x0 = row[lane], x1 = row[lane + 32];
        float as[4], ad[4];
#pragma unroll
        for (int h = 0; h < 4; h++) {
            as[h] = x0 * su[lane][h] + x1 * su[lane + 32][h];
            ad[h] = x0 * sv[lane][h] + x1 * sv[lane + 32][h];
        }
#pragma unroll
        for (int h = 0; h < 4; h++) {
#pragma unroll
            for (int o = 16; o; o >>= 1) {
                as[h] += __shfl_xor_sync(0xFFFFFFFFu, as[h], o);
                ad[h] += __shfl_xor_sync(0xFFFFFFFFu, ad[h], o);
            }
        }
        if (lane == 0) {
            *(float4*)(alS + (size_t)node * 4) = make_float4(as[0], as[1], as[2], as[3]);
            *(float4*)(alD + (size_t)node * 4) = make_float4(ad[0], ad[1], ad[2], ad[3]);
        }
    }
}

// ---------------- TF32 tensor-core GEMM (cp.async double-buffered, R6) -------
__device__ __forceinline__ void mma_tf32(float c[4], const float a[4], const float b[2]) {
    asm volatile(
        "mma.sync.aligned.m16n8k8.row.col.f32.tf32.tf32.f32 "
        "{%0,%1,%2,%3}, {%4,%5,%6,%7}, {%8,%9}, {%0,%1,%2,%3};"
        : "+f"(c[0]), "+f"(c[1]), "+f"(c[2]), "+f"(c[3])
        : "r"(__float_as_uint(a[0])), "r"(__float_as_uint(a[1])),
          "r"(__float_as_uint(a[2])), "r"(__float_as_uint(a[3])),
          "r"(__float_as_uint(b[0])), "r"(__float_as_uint(b[1])));
}

__device__ __forceinline__ void cp_async16(float* smem_dst, const float* gmem_src,
                                           bool pred) {
    uint32_t saddr = (uint32_t)__cvta_generic_to_shared(smem_dst);
    int sz = pred ? 16 : 0;
    asm volatile("cp.async.cg.shared.global [%0], [%1], 16, %2;\n"
                 :: "r"(saddr), "l"(gmem_src), "r"(sz));
}

#define ABUF 4608
#define BBUF 4352
#define SMEM_FLOATS (2 * ABUF + 2 * BBUF)

// C[M,Nc] = op(A)[M,K] @ B[K,Nc]; op = relu(bn) if BNRELU.
// GROUP: A base shifts by (blockN/128)*K columns (head-blocked input).
// ALPHA: accumulates alS/alD[row*4+head] += sum_col C*aS/aD.
template <bool BNRELU, bool ALPHA, bool GROUP>
__global__ __launch_bounds__(256, 2) void tf32gemm(
    const float* __restrict__ A, const float* __restrict__ B,
    float* __restrict__ C, int M, int Nc, int K,
    int lda, int ldb, int ldc,
    const float* __restrict__ scale, const float* __restrict__ shift,
    const float* __restrict__ aS, const float* __restrict__ aD, int Chead,
    float* __restrict__ alS, float* __restrict__ alD)
{
    extern __shared__ float smem[];

    int tid = threadIdx.x;
    int lane = tid & 31;
    int wid = tid >> 5;
    int warpM = (wid >> 2) * 64;
    int warpN = (wid & 3) * 32;
    int r = lane >> 2;
    int cq = lane & 3;

    int blockM = blockIdx.y * 128;
    int blockN = blockIdx.x * 128;

    if (GROUP) A += (size_t)(blockN >> 7) * K;

    int acol = (tid & 7) * 4;
    int arow0 = tid >> 3;
    int bcol = (tid & 31) * 4;
    int brow0 = tid >> 5;

    float acc[4][4][4];
#pragma unroll
    for (int mt = 0; mt < 4; mt++)
#pragma unroll
        for (int nt = 0; nt < 4; nt++)
#pragma unroll
            for (int i = 0; i < 4; i++) acc[mt][nt][i] = 0.0f;

    int nk = K >> 5;

    auto load_tile = [&](int k0, int buf) {
        float* As = smem + buf * ABUF;
        float* Bs = smem + 2 * ABUF + buf * BBUF;
#pragma unroll
        for (int i = 0; i < 4; i++) {
            int row = blockM + arow0 + i * 32;
            cp_async16(&As[(arow0 + i * 32) * 36 + acol],
                       A + (size_t)row * lda + k0 + acol, row < M);
        }
#pragma unroll
        for (int i = 0; i < 4; i++) {
            int kr = brow0 + i * 8;
            cp_async16(&Bs[kr * 136 + bcol],
                       B + (size_t)(k0 + kr) * ldb + blockN + bcol, true);
        }
        asm volatile("cp.async.commit_group;\n");
    };

    load_tile(0, 0);

    for (int kt = 0; kt < nk; kt++) {
        if (kt + 1 < nk) {
            load_tile((kt + 1) << 5, (kt + 1) & 1);
            asm volatile("cp.async.wait_group 1;\n");
        } else {
            asm volatile("cp.async.wait_group 0;\n");
        }
        __syncthreads();

        const float* As = smem + (kt & 1) * ABUF;
        const float* Bs = smem + 2 * ABUF + (kt & 1) * BBUF;
        int k0 = kt << 5;

        float scv[8], shv[8];
        if (BNRELU) {
#pragma unroll
            for (int kk = 0; kk < 4; kk++) {
                scv[kk]     = scale[k0 + kk * 8 + cq];
                scv[kk + 4] = scale[k0 + kk * 8 + cq + 4];
                shv[kk]     = shift[k0 + kk * 8 + cq];
                shv[kk + 4] = shift[k0 + kk * 8 + cq + 4];
            }
        }

#pragma unroll
        for (int kk = 0; kk < 4; kk++) {
            int kb = kk * 8;
            float a[4][4], b[4][2];
#pragma unroll
            for (int mt = 0; mt < 4; mt++) {
                int m = warpM + mt * 16 + r;
                float a0 = As[m * 36 + kb + cq];
                float a1 = As[(m + 8) * 36 + kb + cq];
                float a2 = As[m * 36 + kb + cq + 4];
                float a3 = As[(m + 8) * 36 + kb + cq + 4];
                if (BNRELU) {
                    a0 = fmaxf(fmaf(a0, scv[kk], shv[kk]), 0.f);
                    a1 = fmaxf(fmaf(a1, scv[kk], shv[kk]), 0.f);
                    a2 = fmaxf(fmaf(a2, scv[kk + 4], shv[kk + 4]), 0.f);
                    a3 = fmaxf(fmaf(a3, scv[kk + 4], shv[kk + 4]), 0.f);
                }
                a[mt][0] = a0; a[mt][1] = a1; a[mt][2] = a2; a[mt][3] = a3;
            }
#pragma unroll
            for (int nt = 0; nt < 4; nt++) {
                int nn = warpN + nt * 8 + r;
                b[nt][0] = Bs[(kb + cq) * 136 + nn];
                b[nt][1] = Bs[(kb + cq + 4) * 136 + nn];
            }
#pragma unroll
            for (int mt = 0; mt < 4; mt++)
#pragma unroll
                for (int nt = 0; nt < 4; nt++)
                    mma_tf32(acc[mt][nt], a[mt], b[nt]);
        }
        __syncthreads();
    }

#pragma unroll
    for (int mt = 0; mt < 4; mt++) {
        int row0 = blockM + warpM + mt * 16 + r;
#pragma unroll
        for (int nt = 0; nt < 4; nt++) {
            int col = blockN + warpN + nt * 8 + cq * 2;
            if (row0 < M)
                *(float2*)(C + (size_t)row0 * ldc + col) =
                    make_float2(acc[mt][nt][0], acc[mt][nt][1]);
            if (row0 + 8 < M)
                *(float2*)(C + (size_t)(row0 + 8) * ldc + col) =
                    make_float2(acc[mt][nt][2], acc[mt][nt][3]);
        }
    }

    if (ALPHA) {
        int head = blockN / Chead;
        float ws[4][2], wd[4][2];
#pragma unroll
        for (int nt = 0; nt < 4; nt++) {
            int col = blockN + warpN + nt * 8 + cq * 2;
            int c = col - head * Chead;
            ws[nt][0] = aS[head * Chead + c];
            ws[nt][1] = aS[head * Chead + c + 1];
            wd[nt][0] = aD[head * Chead + c];
            wd[nt][1] = aD[head * Chead + c + 1];
        }
#pragma unroll
        for (int mt = 0; mt < 4; mt++) {
            float ps0 = 0.f, pd0 = 0.f, ps1 = 0.f, pd1 = 0.f;
#pragma unroll
            for (int nt = 0; nt < 4; nt++) {
                ps0 += acc[mt][nt][0] * ws[nt][0] + acc[mt][nt][1] * ws[nt][1];
                pd0 += acc[mt][nt][0] * wd[nt][0] + acc[mt][nt][1] * wd[nt][1];
                ps1 += acc[mt][nt][2] * ws[nt][0] + acc[mt][nt][3] * ws[nt][1];
                pd1 += acc[mt][nt][2] * wd[nt][0] + acc[mt][nt][3] * wd[nt][1];
            }
#pragma unroll
            for (int o = 1; o < 4; o <<= 1) {
                ps0 += __shfl_xor_sync(0xFFFFFFFFu, ps0, o);
                pd0 += __shfl_xor_sync(0xFFFFFFFFu, pd0, o);
                ps1 += __shfl_xor_sync(0xFFFFFFFFu, ps1, o);
                pd1 += __shfl_xor_sync(0xFFFFFFFFu, pd1, o);
            }
            if (cq == 0) {
                int row0 = blockM + warpM + mt * 16 + r;
                if (row0 < M) {
                    atomicAdd(alS + (size_t)row0 * 4 + head, ps0);
                    atomicAdd(alD + (size_t)row0 * 4 + head, pd0);
                }
                if (row0 + 8 < M) {
                    atomicAdd(alS + (size_t)(row0 + 8) * 4 + head, ps1);
                    atomicAdd(alD + (size_t)(row0 + 8) * 4 + head, pd1);
                }
            }
        }
    }
}

// ---------------- fp32 SGEMM (small head GEMMs) ------------------------------
template <bool RELU>
__global__ __launch_bounds__(256) void sgemm(
    const float* __restrict__ A, const float* __restrict__ B,
    const float* __restrict__ bias, float* __restrict__ C,
    int M, int Nc, int K, int lda, int ldc)
{
    __shared__ float As[8][128];
    __shared__ float Bs[8][128];

    int tid = threadIdx.x;
    int bx = blockIdx.x;
    int by = blockIdx.y;

    int tx = tid % 16;
    int ty = tid / 16;

    int rowA = by * 128 + tid / 2;
    int colA = (tid % 2) * 4;
    int rowB = tid / 32;
    int colB = (tid % 32) * 4;

    float acc[8][8];
#pragma unroll
    for (int i = 0; i < 8; i++)
#pragma unroll
        for (int j = 0; j < 8; j++) acc[i][j] = 0.0f;

    for (int k0 = 0; k0 < K; k0 += 8) {
        float4 av = make_float4(0.f, 0.f, 0.f, 0.f);
        if (rowA < M)
            av = *(const float4*)(A + (size_t)rowA * lda + k0 + colA);
        As[colA + 0][tid / 2] = av.x;
        As[colA + 1][tid / 2] = av.y;
        As[colA + 2][tid / 2] = av.z;
        As[colA + 3][tid / 2] = av.w;

        float4 bv = *(const float4*)(B + (size_t)(k0 + rowB) * Nc + bx * 128 + colB);
        *(float4*)(&Bs[rowB][colB]) = bv;

        __syncthreads();

#pragma unroll
        for (int kk = 0; kk < 8; kk++) {
            float ra[8], rb[8];
#pragma unroll
            for (int i = 0; i < 8; i++) ra[i] = As[kk][ty * 8 + i];
#pragma unroll
            for (int j = 0; j < 8; j++) rb[j] = Bs[kk][tx * 8 + j];
#pragma unroll
            for (int i = 0; i < 8; i++)
#pragma unroll
                for (int j = 0; j < 8; j++) acc[i][j] = fmaf(ra[i], rb[j], acc[i][j]);
        }
        __syncthreads();
    }

#pragma unroll
    for (int i = 0; i < 8; i++) {
        int row = by * 128 + ty * 8 + i;
        if (row >= M) continue;
#pragma unroll
        for (int j = 0; j < 8; j++) {
            int col = bx * 128 + tx * 8 + j;
            float v = acc[i][j];
            if (bias) v += bias[col];
            if (RELU) v = v > 0.f ? v : 0.f;
            C[(size_t)row * ldc + col] = v;
        }
    }
}

// ---- GAT layer 1 input-space gather: agg[d, h*64+c] = sum alpha*x[src,c] ----
__global__ __launch_bounds__(64) void gat_agg_in64(
    const int* __restrict__ rowptr, const int* __restrict__ csrsrc,
    const float* __restrict__ alS, const float* __restrict__ alD,
    const float* __restrict__ in, float* __restrict__ agg)
{
    constexpr int NT = 64;
    __shared__ float s_red[8];
    __shared__ float s_bm[4];
    __shared__ float s_binv[4];
    __shared__ float s_al[16][4];
    __shared__ int   s_src[16];

    int d = blockIdx.x;
    int tid = threadIdx.x;
    int lane = tid & 31, w = tid >> 5;
    int beg = rowptr[d], end = rowptr[d + 1];

    float4 ad4 = *(const float4*)(alD + (size_t)d * 4);
    float adv[4] = {ad4.x, ad4.y, ad4.z, ad4.w};

    float mx[4] = {-INFINITY, -INFINITY, -INFINITY, -INFINITY};
    for (int i = beg + tid; i < end; i += NT) {
        int s = csrsrc[i];
        float4 as4 = *(const float4*)(alS + (size_t)s * 4);
        float l[4] = {as4.x + adv[0], as4.y + adv[1], as4.z + adv[2], as4.w + adv[3]};
#pragma unroll
        for (int hh = 0; hh < 4; hh++) {
            float t = l[hh];
            t = t > 0.f ? t : 0.2f * t;
            mx[hh] = fmaxf(mx[hh], t);
        }
    }
#pragma unroll
    for (int hh = 0; hh < 4; hh++)
#pragma unroll
        for (int o = 16; o; o >>= 1)
            mx[hh] = fmaxf(mx[hh], __shfl_xor_sync(0xFFFFFFFFu, mx[hh], o));
    if (lane == 0)
#pragma unroll
        for (int hh = 0; hh < 4; hh++) s_red[w * 4 + hh] = mx[hh];
    __syncthreads();
    if (tid < 4) s_bm[tid] = fmaxf(s_red[tid], s_red[4 + tid]);
    __syncthreads();
    float bm[4] = {s_bm[0], s_bm[1], s_bm[2], s_bm[3]};

    float sme[4] = {0.f, 0.f, 0.f, 0.f};
    for (int i = beg + tid; i < end; i += NT) {
        int s = csrsrc[i];
        float4 as4 = *(const float4*)(alS + (size_t)s * 4);
        float l[4] = {as4.x + adv[0], as4.y + adv[1], as4.z + adv[2], as4.w + adv[3]};
#pragma unroll
        for (int hh = 0; hh < 4; hh++) {
            float t = l[hh];
            t = t > 0.f ? t : 0.2f * t;
            sme[hh] += expf(t - bm[hh]);
        }
    }
#pragma unroll
    for (int hh = 0; hh < 4; hh++)
#pragma unroll
        for (int o = 16; o; o >>= 1)
            sme[hh] += __shfl_xor_sync(0xFFFFFFFFu, sme[hh], o);
    if (lane == 0)
#pragma unroll
        for (int hh = 0; hh < 4; hh++) s_red[w * 4 + hh] = sme[hh];
    __syncthreads();
    if (tid < 4) s_binv[tid] = 1.0f / fmaxf(s_red[tid] + s_red[4 + tid], 1e-16f);
    __syncthreads();

    float acc[4] = {0.f, 0.f, 0.f, 0.f};
    for (int c0 = beg; c0 < end; c0 += 16) {
        int cnt = min(16, end - c0);
        if (tid < cnt * 4) {
            int j = tid >> 2, hh = tid & 3;
            int s = csrsrc[c0 + j];
            if (hh == 0) s_src[j] = s;
            float t = alS[(size_t)s * 4 + hh] + adv[hh];
            t = t > 0.f ? t : 0.2f * t;
            s_al[j][hh] = expf(t - s_bm[hh]) * s_binv[hh];
        }
        __syncthreads();
        for (int j = 0; j < cnt; j++) {
            float v = in[(size_t)s_src[j] * 64 + tid];
#pragma unroll
            for (int hh = 0; hh < 4; hh++)
                acc[hh] = fmaf(s_al[j][hh], v, acc[hh]);
        }
        __syncthreads();
    }

#pragma unroll
    for (int hh = 0; hh < 4; hh++)
        agg[(size_t)d * 256 + hh * 64 + tid] = acc[hh];
}

// ---- fused per-destination GAT softmax + gather (output space) --------------
// HC=512: one block per node (grid.y=1, SPLIT=1). HC=1024: two blocks per node
// (grid.y=2), each handling a 512-channel half (2 heads).
template <int HC, int SPLIT>
__global__ __launch_bounds__(128) void gat_gather(
    const int* __restrict__ rowptr, const int* __restrict__ csrsrc,
    const float* __restrict__ alS, const float* __restrict__ alD,
    const float* __restrict__ h, float* __restrict__ out)
{
    constexpr int NT = 128;
    constexpr int HCW = HC / SPLIT;          // channels this block owns
    constexpr int VEC = HCW / (4 * NT);      // float4s per thread
    constexpr int CPH = HC / 4;              // channels per head

    __shared__ float s_red[16];
    __shared__ float s_bm[4];
    __shared__ float s_binv[4];
    __shared__ float s_al[32][4];
    __shared__ int   s_src[32];

    int d = blockIdx.x;
    int half = (SPLIT > 1) ? blockIdx.y : 0;
    int coff = half * HCW;                   // channel offset of this block
    int tid = threadIdx.x;
    int lane = tid & 31, w = tid >> 5;
    int beg = rowptr[d], end = rowptr[d + 1];

    float4 ad4 = *(const float4*)(alD + (size_t)d * 4);
    float adv[4] = {ad4.x, ad4.y, ad4.z, ad4.w};

    float mx[4] = {-INFINITY, -INFINITY, -INFINITY, -INFINITY};
    for (int i = beg + tid; i < end; i += NT) {
        int s = csrsrc[i];
        float4 as4 = *(const float4*)(alS + (size_t)s * 4);
        float l[4] = {as4.x + adv[0], as4.y + adv[1], as4.z + adv[2], as4.w + adv[3]};
#pragma unroll
        for (int hh = 0; hh < 4; hh++) {
            float t = l[hh];
            t = t > 0.f ? t : 0.2f * t;
            mx[hh] = fmaxf(mx[hh], t);
        }
    }
#pragma unroll
    for (int hh = 0; hh < 4; hh++)
#pragma unroll
        for (int o = 16; o; o >>= 1)
            mx[hh] = fmaxf(mx[hh], __shfl_xor_sync(0xFFFFFFFFu, mx[hh], o));
    if (lane == 0)
#pragma unroll
        for (int hh = 0; hh < 4; hh++) s_red[w * 4 + hh] = mx[hh];
    __syncthreads();
    if (tid < 4) {
        float r = fmaxf(fmaxf(s_red[tid], s_red[4 + tid]),
                        fmaxf(s_red[8 + tid], s_red[12 + tid]));
        s_bm[tid] = r;
    }
    __syncthreads();
    float bm[4] = {s_bm[0], s_bm[1], s_bm[2], s_bm[3]};

    float sme[4] = {0.f, 0.f, 0.f, 0.f};
    for (int i = beg + tid; i < end; i += NT) {
        int s = csrsrc[i];
        float4 as4 = *(const float4*)(alS + (size_t)s * 4);
        float l[4] = {as4.x + adv[0], as4.y + adv[1], as4.z + adv[2], as4.w + adv[3]};
#pragma unroll
        for (int hh = 0; hh < 4; hh++) {
            float t = l[hh];
            t = t > 0.f ? t : 0.2f * t;
            sme[hh] += expf(t - bm[hh]);
        }
    }
#pragma unroll
    for (int hh = 0; hh < 4; hh++)
#pragma unroll
        for (int o = 16; o; o >>= 1)
            sme[hh] += __shfl_xor_sync(0xFFFFFFFFu, sme[hh], o);
    if (lane == 0)
#pragma unroll
        for (int hh = 0; hh < 4; hh++) s_red[w * 4 + hh] = sme[hh];
    __syncthreads();
    if (tid < 4) {
        float r = s_red[tid] + s_red[4 + tid] + s_red[8 + tid] + s_red[12 + tid];
        s_binv[tid] = 1.0f / fmaxf(r, 1e-16f);
    }
    __syncthreads();

    float4 acc[VEC];
#pragma unroll
    for (int v = 0; v < VEC; v++) acc[v] = make_float4(0.f, 0.f, 0.f, 0.f);

    int headOf[VEC];
#pragma unroll
    for (int v = 0; v < VEC; v++) headOf[v] = (coff + tid * 4 + v * NT * 4) / CPH;

    for (int c0 = beg; c0 < end; c0 += 32) {
        int cnt = min(32, end - c0);
        if (tid < cnt * 4) {
            int j = tid >> 2, hh = tid & 3;
            int s = csrsrc[c0 + j];
            if (hh == 0) s_src[j] = s;
            float t = alS[(size_t)s * 4 + hh] + adv[hh];
            t = t > 0.f ? t : 0.2f * t;
            s_al[j][hh] = expf(t - s_bm[hh]) * s_binv[hh];
        }
        __syncthreads();
        for (int j = 0; j < cnt; j++) {
            int s = s_src[j];
            const float4* hp = (const float4*)(h + (size_t)s * HC + coff);
#pragma unroll
            for (int v = 0; v < VEC; v++) {
                float a = s_al[j][headOf[v]];
                float4 hv = hp[tid + v * NT];
                acc[v].x = fmaf(a, hv.x, acc[v].x);
                acc[v].y = fmaf(a, hv.y, acc[v].y);
                acc[v].z = fmaf(a, hv.z, acc[v].z);
                acc[v].w = fmaf(a, hv.w, acc[v].w);
            }
        }
        __syncthreads();
    }

    float4* op = (float4*)(out + (size_t)d * HC + coff);
#pragma unroll
    for (int v = 0; v < VEC; v++) op[tid + v * NT] = acc[v];
}

// ---------------- GCN gather -------------------------------------------------
__global__ __launch_bounds__(64) void gcn_gather(
    const int* __restrict__ rowptr, const int* __restrict__ csrsrc,
    const float* __restrict__ dinv, const float* __restrict__ h,
    float* __restrict__ out)
{
    int d = blockIdx.x;
    int tid = threadIdx.x;
    int beg = rowptr[d], end = rowptr[d + 1];
    float dd = dinv[d];

    float4 acc = make_float4(0.f, 0.f, 0.f, 0.f);
    for (int i = beg; i < end; i++) {
        int s = csrsrc[i];
        float nrm = dinv[s] * dd;
        float4 v = *(const float4*)(h + (size_t)s * 256 + tid * 4);
        acc.x = fmaf(nrm, v.x, acc.x);
        acc.y = fmaf(nrm, v.y, acc.y);
        acc.z = fmaf(nrm, v.z, acc.z);
        acc.w = fmaf(nrm, v.w, acc.w);
    }
    *(float4*)(out + (size_t)d * 256 + tid * 4) = acc;
}

// ---------------- BatchNorm -------------------------------------------------
__global__ void bn_stats(const float* __restrict__ x, int rows, int K,
                         float* __restrict__ sum, float* __restrict__ sq)
{
    int col = blockIdx.x * blockDim.x + threadIdx.x;
    float s = 0.f, q = 0.f;
    for (int r = blockIdx.y; r < rows; r += gridDim.y) {
        float v = x[(size_t)r * K + col];
        s += v;
        q += v * v;
    }
    atomicAdd(sum + col, s);
    atomicAdd(sq + col, q);
}

__global__ void bn_finalize(const float* __restrict__ sum, const float* __restrict__ sq,
                            const float* __restrict__ g, const float* __restrict__ b,
                            int rows, int K, float* __restrict__ scale,
                            float* __restrict__ shift)
{
    int c = blockIdx.x * blockDim.x + threadIdx.x;
    if (c >= K) return;
    float inv_n = 1.0f / (float)rows;
    float mu = sum[c] * inv_n;
    float var = sq[c] * inv_n - mu * mu;
    float sc = g[c] * rsqrtf(var + 1e-5f);
    scale[c] = sc;
    shift[c] = b[c] - mu * sc;
}

__global__ void bn_apply_relu(float* __restrict__ x, const float* __restrict__ scale,
                              const float* __restrict__ shift, size_t total, int K)
{
    for (size_t i = (size_t)blockIdx.x * blockDim.x + threadIdx.x; i < total;
         i += (size_t)gridDim.x * blockDim.x) {
        int c = (int)(i % K);
        float v = x[i] * scale[c] + shift[c];
        x[i] = v > 0.f ? v : 0.f;
    }
}

// ---------------- Pooling: one block per graph (batch sorted, no atomics) ----
__global__ __launch_bounds__(256) void pool_graph(
    const float* __restrict__ h, const int* __restrict__ gstart,
    const float* __restrict__ scale, const float* __restrict__ shift,
    float* __restrict__ z)
{
    int g = blockIdx.x;
    int c = threadIdx.x;
    int beg = gstart[g], end = gstart[g + 1];
    float sc = scale[c], sh = shift[c];
    float sum = 0.f, mx = 0.f;
    for (int r = beg; r < end; r++) {
        float v = fmaxf(fmaf(h[(size_t)r * 256 + c], sc, sh), 0.f);
        sum += v;
        mx = fmaxf(mx, v);
    }
    float cnt = (float)(end - beg);
    z[(size_t)g * 640 + c] = sum / fmaxf(cnt, 1.0f);
    z[(size_t)g * 640 + 256 + c] = mx;
}

// ---------------- Head -------------------------------------------------------
__global__ void head_final(const float* __restrict__ zf, const float* __restrict__ Wf2,
                           const float* __restrict__ bf2, float* __restrict__ out)
{
    int g = blockIdx.x;
    int t = threadIdx.x;
    float v = zf[(size_t)g * 128 + t] * Wf2[t];
#pragma unroll
    for (int o = 16; o; o >>= 1) v += __shfl_down_sync(0xFFFFFFFFu, v, o);
    __shared__ float sm[4];
    if ((t & 31) == 0) sm[t >> 5] = v;
    __syncthreads();
    if (t == 0) {
        float s = sm[0] + sm[1] + sm[2] + sm[3] + bf2[0];
        out[g] = 1.0f / (1.0f + expf(-s));
    }
}

// ---------------- launch ------------------------------------------------------
extern "C" void kernel_launch(void* const* d_in, const int* in_sizes, int n_in,
                              void* d_out, int out_size)
{
    const float* x    = (const float*)d_in[0];
    const int*   ei   = (const int*)d_in[1];
    const int*   batch= (const int*)d_in[2];
    const float* fp   = (const float*)d_in[3];
    const float* W1   = (const float*)d_in[4];
    const float* a1s  = (const float*)d_in[5];
    const float* a1d  = (const float*)d_in[6];
    const float* bn1g = (const float*)d_in[8];
    const float* bn1b = (const float*)d_in[9];
    const float* W2   = (const float*)d_in[10];
    const float* a2s  = (const float*)d_in[11];
    const float* a2d  = (const float*)d_in[12];
    const float* bn2g = (const float*)d_in[14];
    const float* bn2b = (const float*)d_in[15];
    const float* Wg   = (const float*)d_in[16];
    const float* bn3g = (const float*)d_in[18];
    const float* bn3b = (const float*)d_in[19];
    const float* Ws   = (const float*)d_in[20];
    const float* bs   = (const float*)d_in[21];
    const float* Wf1  = (const float*)d_in[22];
    const float* bnfg = (const float*)d_in[24];
    const float* bnfb = (const float*)d_in[25];
    const float* Wf2  = (const float*)d_in[26];
    const float* bf2  = (const float*)d_in[27];
    float* out = (float*)d_out;

    int n    = in_sizes[0] / 64;
    int E    = in_sizes[1] / 2;
    int Etot = E + n;
    int G    = in_sizes[3] / 128;

    float *bufA, *bufB, *bufC, *alS, *alD, *dinv, *uu, *vv;
    float *bnsum, *bnsq, *bnscale, *bnshift, *z, *zf;
    int *degi, *rowptr, *cursor, *csrsrc, *gstart;
    cudaGetSymbolAddress((void**)&bufA, g_bufA);
    cudaGetSymbolAddress((void**)&bufB, g_bufB);
    cudaGetSymbolAddress((void**)&bufC, g_bufC);
    cudaGetSymbolAddress((void**)&alS, g_alS);
    cudaGetSymbolAddress((void**)&alD, g_alD);
    cudaGetSymbolAddress((void**)&uu, g_u);
    cudaGetSymbolAddress((void**)&vv, g_v);
    cudaGetSymbolAddress((void**)&degi, g_degi);
    cudaGetSymbolAddress((void**)&rowptr, g_rowptr);
    cudaGetSymbolAddress((void**)&cursor, g_cursor);
    cudaGetSymbolAddress((void**)&csrsrc, g_csrsrc);
    cudaGetSymbolAddress((void**)&dinv, g_dinv);
    cudaGetSymbolAddress((void**)&gstart, g_gstart);
    cudaGetSymbolAddress((void**)&bnsum, g_bnsum);
    cudaGetSymbolAddress((void**)&bnsq, g_bnsq);
    cudaGetSymbolAddress((void**)&bnscale, g_bnscale);
    cudaGetSymbolAddress((void**)&bnshift, g_bnshift);
    cudaGetSymbolAddress((void**)&z, g_z);
    cudaGetSymbolAddress((void**)&zf, g_zf);

    size_t smem_bytes = SMEM_FLOATS * sizeof(float);
    static bool attr_done = false;
    if (!attr_done) {
        cudaFuncSetAttribute(tf32gemm<false, false, true>,
                             cudaFuncAttributeMaxDynamicSharedMemorySize, (int)smem_bytes);
        cudaFuncSetAttribute(tf32gemm<true, true, false>,
                             cudaFuncAttributeMaxDynamicSharedMemorySize, (int)smem_bytes);
        cudaFuncSetAttribute(tf32gemm<true, false, false>,
                             cudaFuncAttributeMaxDynamicSharedMemorySize, (int)smem_bytes);
        attr_done = true;
    }

    auto gemm = [&](const float* A, const float* B, const float* bias, float* C,
                    int M, int Nc, int K, int lda, int ldc, bool relu) {
        dim3 grid(Nc / 128, (M + 127) / 128);
        if (relu) sgemm<true><<<grid, 256>>>(A, B, bias, C, M, Nc, K, lda, ldc);
        else      sgemm<false><<<grid, 256>>>(A, B, bias, C, M, Nc, K, lda, ldc);
    };

    auto bnstats = [&](const float* Xp, int rows, int K, const float* gg,
                       const float* bb) {
        cudaMemsetAsync(bnsum, 0, K * sizeof(float));
        cudaMemsetAsync(bnsq, 0, K * sizeof(float));
        dim3 g1(K / 128, 128);
        bn_stats<<<g1, 128>>>(Xp, rows, K, bnsum, bnsq);
        bn_finalize<<<(K + 127) / 128, 128>>>(bnsum, bnsq, gg, bb, rows, K,
                                              bnscale, bnshift);
    };

    // ---- CSR build (dst-sorted), reused by GAT1/GAT2/GCN; graph boundaries
    cudaMemsetAsync(degi, 0, n * sizeof(int));
    deg_build<<<(Etot + 255) / 256, 256>>>(ei, E, Etot, degi);
    scan_kernel<<<1, 1024>>>(degi, rowptr, cursor, n);
    csr_scatter<<<(Etot + 255) / 256, 256>>>(ei, E, Etot, cursor, csrsrc);
    dinv_kernel<<<(n + 255) / 256, 256>>>(rowptr, dinv, n);
    gstart_build<<<(n + 256) / 256, 256>>>(batch, n, G, gstart);

    // ---- GAT layer 1 (input-space): alphas exact via u=W1·a; gather x; GEMM
    uv_build<<<(64 * 4 * 32 + 255) / 256, 256>>>(W1, a1s, a1d, 64, 128, uu, vv);
    alpha_gemm64<<<(n + 7) / 8, 256>>>(x, n, uu, vv, alS, alD);
    gat_agg_in64<<<n, 64>>>(rowptr, csrsrc, alS, alD, x, bufA);
    {
        dim3 grid(4, (n + 127) / 128);
        tf32gemm<false, false, true><<<grid, 256, smem_bytes>>>(
            bufA, W1, bufB, n, 512, 64, 256, 512, 512,
            nullptr, nullptr, nullptr, nullptr, 128, nullptr, nullptr);
    }
    bnstats(bufB, n, 512, bn1g, bn1b);

    // ---- GAT layer 2: bufC = relu(bn(bufB))@W2 (+ fused alphas); gather -> bufA
    cudaMemsetAsync(alS, 0, (size_t)n * 4 * sizeof(float));
    cudaMemsetAsync(alD, 0, (size_t)n * 4 * sizeof(float));
    {
        dim3 grid(8, (n + 127) / 128);
        tf32gemm<true, true, false><<<grid, 256, smem_bytes>>>(
            bufB, W2, bufC, n, 1024, 512, 512, 1024, 1024,
            bnscale, bnshift, a2s, a2d, 256, alS, alD);
    }
    {
        dim3 grid(n, 2);
        gat_gather<1024, 2><<<grid, 128>>>(rowptr, csrsrc, alS, alD, bufC, bufA);
    }
    bnstats(bufA, n, 1024, bn2g, bn2b);

    // ---- GCN: bufB[N,256] = relu(bn(bufA))@Wg; gather -> bufC; BN stats
    {
        dim3 grid(2, (n + 127) / 128);
        tf32gemm<true, false, false><<<grid, 256, smem_bytes>>>(
            bufA, Wg, bufB, n, 256, 1024, 1024, 256, 256,
            bnscale, bnshift, nullptr, nullptr, 256, nullptr, nullptr);
    }
    gcn_gather<<<n, 64>>>(rowptr, csrsrc, dinv, bufB, bufC);
    bnstats(bufC, n, 256, bn3g, bn3b);

    // ---- Pooling into z[G,640] (block per graph; BN+relu on the fly)
    pool_graph<<<G, 256>>>(bufC, gstart, bnscale, bnshift, z);

    // ---- solvent MLP: relu(fp @ Ws + bs) -> z[:,512:640]
    gemm(fp, Ws, bs, z + 512, G, 128, 128, 128, 640, true);

    // ---- head: zf = z @ Wf1 (bf1 cancels under BN); BN; relu; sigmoid
    gemm(z, Wf1, nullptr, zf, G, 128, 640, 640, 128, false);
    {
        cudaMemsetAsync(bnsum, 0, 128 * sizeof(float));
        cudaMemsetAsync(bnsq, 0, 128 * sizeof(float));
        dim3 g1(1, 128);
        bn_stats<<<g1, 128>>>(zf, G, 128, bnsum, bnsq);
        bn_finalize<<<1, 128>>>(bnsum, bnsq, bnfg, bnfb, G, 128, bnscale, bnshift);
        bn_apply_relu<<<((size_t)G * 128 + 255) / 256, 256>>>(zf, bnscale, bnshift,
                                                              (size_t)G * 128, 128);
    }
    head_final<<<G, 128>>>(zf, Wf2, bf2, out);
}